// round 2
// baseline (speedup 1.0000x reference)
#include <cuda_runtime.h>
#include <cuda_bf16.h>
#include <cstdint>

#define NM    512
#define BATCH 32
#define DIMK  64
#define WARPS 16
#define BIGF  1e30f
#define SENTINEL 0x7fc00000u

// Padded scratch for D (pre-scaled by log2(e)), layout D[b][j][i].
// LO pad covers prefetch indices down to -23 rows; HI pad up to +40 rows.
#define DPAD_LO 16384
#define DPAD_HI 32768
__device__ float g_D[DPAD_LO + (size_t)BATCH * NM * NM + DPAD_HI];

__device__ __forceinline__ float ex2f(float x) {
    float r; asm("ex2.approx.f32 %0, %1;" : "=f"(r) : "f"(x)); return r;
}
__device__ __forceinline__ float lg2f(float x) {
    float r; asm("lg2.approx.f32 %0, %1;" : "=f"(r) : "f"(x)); return r;
}

// ---------------------------------------------------------------------------
// Kernel 1: D[b][j][i] = (||X[b,i]||^2 + ||Y[b,j]||^2 - 2 X.Y) * log2(e)
// 64x64 tiles, 256 threads, 4x4 register microtile per thread.
// ---------------------------------------------------------------------------
__global__ void __launch_bounds__(256) pairdist_kernel(
    const float* __restrict__ X, const float* __restrict__ Y)
{
    __shared__ __align__(16) float Xs[64 * 68];
    __shared__ __align__(16) float Ys[64 * 68];
    __shared__ __align__(16) float x2s[64];
    __shared__ __align__(16) float y2s[64];

    const int b  = blockIdx.z;
    const int i0 = blockIdx.x * 64;
    const int j0 = blockIdx.y * 64;
    const int tid = threadIdx.x;

    const float* Xb = X + ((size_t)b * NM + i0) * DIMK;
    const float* Yb = Y + ((size_t)b * NM + j0) * DIMK;

    // Load tiles transposed: Xs[k*68 + row], coalesced global reads.
    for (int t = tid; t < 64 * 64; t += 256) {
        int r = t >> 6, k = t & 63;
        Xs[k * 68 + r] = Xb[r * DIMK + k];
        Ys[k * 68 + r] = Yb[r * DIMK + k];
    }
    __syncthreads();

    // Row norms
    if (tid < 128) {
        int r = tid & 63;
        const float* S = (tid < 64) ? Xs : Ys;
        float acc = 0.f;
        #pragma unroll 8
        for (int k = 0; k < 64; ++k) { float v = S[k * 68 + r]; acc += v * v; }
        if (tid < 64) x2s[r] = acc; else y2s[r] = acc;
    }
    __syncthreads();

    const int tx = tid & 15;   // i microtile
    const int ty = tid >> 4;   // j microtile
    float acc[4][4];
    #pragma unroll
    for (int a = 0; a < 4; ++a)
        #pragma unroll
        for (int c = 0; c < 4; ++c) acc[a][c] = 0.f;

    #pragma unroll 8
    for (int k = 0; k < 64; ++k) {
        float4 xv = *(const float4*)&Xs[k * 68 + 4 * tx];
        float4 yv = *(const float4*)&Ys[k * 68 + 4 * ty];
        float xr[4] = {xv.x, xv.y, xv.z, xv.w};
        float yr[4] = {yv.x, yv.y, yv.z, yv.w};
        #pragma unroll
        for (int jj = 0; jj < 4; ++jj)
            #pragma unroll
            for (int ii = 0; ii < 4; ++ii)
                acc[jj][ii] += yr[jj] * xr[ii];
    }

    const float L2E = 1.4426950408889634f;
    float4 x2v = *(const float4*)&x2s[4 * tx];
    float* outp = g_D + DPAD_LO + ((size_t)b * NM + (j0 + 4 * ty)) * NM + i0 + 4 * tx;
    #pragma unroll
    for (int jj = 0; jj < 4; ++jj) {
        float y2 = y2s[4 * ty + jj];
        float4 dv;
        dv.x = (x2v.x + y2 - 2.f * acc[jj][0]) * L2E;
        dv.y = (x2v.y + y2 - 2.f * acc[jj][1]) * L2E;
        dv.z = (x2v.z + y2 - 2.f * acc[jj][2]) * L2E;
        dv.w = (x2v.w + y2 - 2.f * acc[jj][3]) * L2E;
        *(float4*)(outp + (size_t)jj * NM) = dv;
    }
}

// ---------------------------------------------------------------------------
// Kernel 2: soft-DTW wavefront DP. One CTA per batch, 512 threads.
// Lane k of warp w owns row i = 32w+k; at step s it computes column j = s-k.
// Warp boundaries stream through smem; the value word is its own ready-flag
// (sentinel bit pattern; DP never produces NaN bits).
// Everything runs in the xlog2(e) domain: softmin = m - log2(sum 2^(m-r)).
// ---------------------------------------------------------------------------
__global__ void __launch_bounds__(512, 1) sdtw_kernel(float* __restrict__ out)
{
    __shared__ float buf[(WARPS + 1) * NM];   // row 0: virtual BIG row; row w+1: warp w bottom

    const int b    = blockIdx.x;
    const int tid  = threadIdx.x;
    const int w    = tid >> 5;
    const int lane = tid & 31;
    const int i    = tid;                      // global row

    // Init boundary buffer: row 0 = BIG, rest = sentinel
    for (int t = tid; t < (WARPS + 1) * NM; t += 512)
        buf[t] = (t < NM) ? BIGF : __uint_as_float(SENTINEL);
    __syncthreads();

    // Prefetch ring for D[b][j][i] (scaled), pointer walks j with stride NM.
    const float* dp = g_D + DPAD_LO + (size_t)b * NM * NM + i + (size_t)(8 - lane) * NM;
    float dring[8];
    #pragma unroll
    for (int p = 0; p < 8; ++p) dring[p] = dp[(p - 8) * NM];

    float val  = BIGF;
    float left = BIGF;
    float up2  = (tid == 0) ? 0.0f : BIGF;     // Rc[-1][-1] = 0 only at origin
    float up1  = BIGF;
    if (lane == 0) {
        volatile float* p = &buf[w * NM + 0];
        float v = *p;
        while (__float_as_uint(v) == SENTINEL) v = *p;
        up1 = v;                                // warp0 reads BIG row -> BIG
    }

    #pragma unroll 8
    for (int s = 0; s < 544; ++s) {
        float d = dring[s & 7];
        dring[s & 7] = *dp; dp += NM;           // prefetch step s+8 (pads absorb OOB)

        // softmin in log2 domain (unconditional; inactive lanes carry BIG)
        float m  = fminf(fminf(up2, up1), left);
        float e0 = ex2f(m - up2);
        float e1 = ex2f(m - up1);
        float e2 = ex2f(m - left);
        float lg = lg2f(e0 + e1 + e2);
        float v  = d + (m - lg);

        int  j   = s - lane;
        bool act = (unsigned)j < (unsigned)NM;
        if (act) { val = v; left = v; }
        if (act && lane == 31)
            *(volatile float*)&buf[(w + 1) * NM + j] = v;

        float sh = __shfl_up_sync(0xffffffffu, val, 1);
        up2 = up1;
        up1 = sh;
        if (lane == 0) {
            int jn = s + 1;
            float bv = BIGF;
            if (jn < NM) {
                volatile float* p = &buf[w * NM + jn];
                bv = *p;
                while (__float_as_uint(bv) == SENTINEL) bv = *p;
            }
            up1 = bv;
        }
    }

    if (tid == 511)
        out[b] = val * 0.69314718055994531f;    // back out of log2 domain (/log2(e))
}

extern "C" void kernel_launch(void* const* d_in, const int* in_sizes, int n_in,
                              void* d_out, int out_size)
{
    (void)in_sizes; (void)n_in; (void)out_size;
    const float* X = (const float*)d_in[0];
    const float* Y = (const float*)d_in[1];
    float* out = (float*)d_out;

    dim3 g1(NM / 64, NM / 64, BATCH);
    pairdist_kernel<<<g1, 256>>>(X, Y);
    sdtw_kernel<<<BATCH, 512>>>(out);
}

// round 4
// speedup vs baseline: 3.3440x; 3.3440x over previous
#include <cuda_runtime.h>
#include <cuda_bf16.h>
#include <cstdint>

#define NM     512
#define BATCH  32
#define DIMK   64
#define WARPS  16
#define BIGF   1e30f
#define SENTINEL 0x7fc00000u

// Diagonal layout: Dd[b][t][i], t = i+j in [0,1022], row stride 512.
// 1024 rows per batch; +32 rows pad for prefetch overrun on the last batch.
#define TROWS   1024
#define BSTRIDE (TROWS * NM)
__device__ float g_Dd[(size_t)BATCH * BSTRIDE + 16384];

__device__ __forceinline__ float ex2f(float x) {
    float r; asm("ex2.approx.f32 %0, %1;" : "=f"(r) : "f"(x)); return r;
}
__device__ __forceinline__ float lg2f(float x) {
    float r; asm("lg2.approx.f32 %0, %1;" : "=f"(r) : "f"(x)); return r;
}

// ---------------------------------------------------------------------------
// Kernel 1: Dd[b][i+j][i] = (||X[b,i]||^2 + ||Y[b,j]||^2 - 2 X.Y) * log2(e)
// 64x64 tiles, 256 threads, 4x4 microtile; diagonal-coalesced writeout.
// ---------------------------------------------------------------------------
__global__ void __launch_bounds__(256) pairdist_kernel(
    const float* __restrict__ X, const float* __restrict__ Y)
{
    __shared__ __align__(16) float Xs[64 * 68];
    __shared__ __align__(16) float Ys[64 * 68];
    __shared__ __align__(16) float x2s[64];
    __shared__ __align__(16) float y2s[64];
    __shared__ __align__(16) float stage[64 * 64];   // stage[j_local][i_local]

    const int b  = blockIdx.z;
    const int i0 = blockIdx.x * 64;
    const int j0 = blockIdx.y * 64;
    const int tid = threadIdx.x;

    const float* Xb = X + ((size_t)b * NM + i0) * DIMK;
    const float* Yb = Y + ((size_t)b * NM + j0) * DIMK;

    for (int t = tid; t < 64 * 64; t += 256) {
        int r = t >> 6, k = t & 63;
        Xs[k * 68 + r] = Xb[r * DIMK + k];
        Ys[k * 68 + r] = Yb[r * DIMK + k];
    }
    __syncthreads();

    if (tid < 128) {
        int r = tid & 63;
        const float* S = (tid < 64) ? Xs : Ys;
        float acc = 0.f;
        #pragma unroll 8
        for (int k = 0; k < 64; ++k) { float v = S[k * 68 + r]; acc += v * v; }
        if (tid < 64) x2s[r] = acc; else y2s[r] = acc;
    }
    __syncthreads();

    const int tx = tid & 15;   // i microtile
    const int ty = tid >> 4;   // j microtile
    float acc[4][4];
    #pragma unroll
    for (int a = 0; a < 4; ++a)
        #pragma unroll
        for (int c = 0; c < 4; ++c) acc[a][c] = 0.f;

    #pragma unroll 8
    for (int k = 0; k < 64; ++k) {
        float4 xv = *(const float4*)&Xs[k * 68 + 4 * tx];
        float4 yv = *(const float4*)&Ys[k * 68 + 4 * ty];
        float xr[4] = {xv.x, xv.y, xv.z, xv.w};
        float yr[4] = {yv.x, yv.y, yv.z, yv.w};
        #pragma unroll
        for (int jj = 0; jj < 4; ++jj)
            #pragma unroll
            for (int ii = 0; ii < 4; ++ii)
                acc[jj][ii] += yr[jj] * xr[ii];
    }

    const float L2E = 1.4426950408889634f;
    float4 x2v = *(const float4*)&x2s[4 * tx];
    float xr2[4] = {x2v.x, x2v.y, x2v.z, x2v.w};
    #pragma unroll
    for (int jj = 0; jj < 4; ++jj) {
        float y2 = y2s[4 * ty + jj];
        #pragma unroll
        for (int ii = 0; ii < 4; ++ii)
            stage[(4 * ty + jj) * 64 + 4 * tx + ii] =
                (xr2[ii] + y2 - 2.f * acc[jj][ii]) * L2E;
    }
    __syncthreads();

    // Diagonal-coalesced writeout: tile diag td -> global row t = i0+j0+td.
    // Diagonal length can reach 64 -> stride the 32 lanes across it.
    const int w    = tid >> 5;
    const int lane = tid & 31;
    const int tbase = i0 + j0;
    float* gout = g_Dd + (size_t)blockIdx.z * BSTRIDE;
    for (int td = w; td < 127; td += 8) {
        int lo = td > 63 ? td - 63 : 0;
        int hi = td < 63 ? td : 63;
        for (int il = lo + lane; il <= hi; il += 32) {
            float v = stage[(td - il) * 64 + il];
            gout[(size_t)(tbase + td) * NM + i0 + il] = v;
        }
    }
}

// ---------------------------------------------------------------------------
// Kernel 2: soft-DTW wavefront. One CTA per batch, 16 warps; lane k of warp w
// owns row i=32w+k; at step s it computes j=s-lane. All D loads hit one line
// (diag layout: Dd[32w+s][32w+lane]). Boundary rows stream through smem; the
// data word is its own ready flag (sentinel NaN). Branchless broadcast poll.
// ---------------------------------------------------------------------------
__global__ void __launch_bounds__(512, 1) sdtw_kernel(float* __restrict__ out)
{
    __shared__ float buf[(WARPS + 1) * NM];

    const int b    = blockIdx.x;
    const int tid  = threadIdx.x;
    const int w    = tid >> 5;
    const int lane = tid & 31;

    for (int t = tid; t < (WARPS + 1) * NM; t += 512)
        buf[t] = (t < NM) ? BIGF : __uint_as_float(SENTINEL);
    __syncthreads();

    // Prefetch ring: at step s consume Dd row t=32w+s, prefetch row 32w+s+8.
    const float* dp = g_Dd + (size_t)b * BSTRIDE + (size_t)(32 * w + 8) * NM + 32 * w + lane;
    float dring[8];
    #pragma unroll
    for (int p = 0; p < 8; ++p) dring[p] = dp[(p - 8) * NM];

    float val  = BIGF;
    float left = BIGF;
    float up2  = (tid == 0) ? 0.0f : BIGF;
    float up1;
    {
        volatile float* p = &buf[w * NM];
        float bv = *p;
        while (__float_as_uint(bv) == SENTINEL) bv = *p;
        up1 = (lane == 0) ? bv : BIGF;
    }

    #pragma unroll 8
    for (int s = 0; s < 544; ++s) {
        float d = dring[s & 7];
        dring[s & 7] = *dp; dp += NM;

        // softmin in log2 domain
        float m  = fminf(fminf(up2, up1), left);
        float e0 = ex2f(m - up2);
        float e1 = ex2f(m - up1);
        float e2 = ex2f(m - left);
        float lg = lg2f(e0 + e1 + e2);
        float v  = d + (m - lg);

        int  j   = s - lane;
        bool act = (unsigned)j < (unsigned)NM;
        if (act) { val = v; left = v; }
        if (lane == 31 && act)
            *(volatile float*)&buf[(w + 1) * NM + j] = v;   // predicated STS

        // boundary value for next step (j = s+1), uniform broadcast poll
        int jn = s + 1; if (jn > NM - 1) jn = NM - 1;
        volatile float* p = &buf[w * NM + jn];
        float bv = *p;
        while (__float_as_uint(bv) == SENTINEL) bv = *p;

        float sh = __shfl_up_sync(0xffffffffu, val, 1);
        up2 = up1;
        up1 = (lane == 0) ? bv : sh;
    }

    if (tid == 511)
        out[b] = val * 0.69314718055994531f;   // log2 -> natural domain
}

extern "C" void kernel_launch(void* const* d_in, const int* in_sizes, int n_in,
                              void* d_out, int out_size)
{
    (void)in_sizes; (void)n_in; (void)out_size;
    const float* X = (const float*)d_in[0];
    const float* Y = (const float*)d_in[1];
    float* out = (float*)d_out;

    dim3 g1(NM / 64, NM / 64, BATCH);
    pairdist_kernel<<<g1, 256>>>(X, Y);
    sdtw_kernel<<<BATCH, 512>>>(out);
}

// round 5
// speedup vs baseline: 3.9104x; 1.1694x over previous
#include <cuda_runtime.h>
#include <cuda_bf16.h>
#include <cstdint>

#define NM     512
#define BATCH  32
#define DIMK   64
#define WARPS  16
#define BIGF   1e30f
#define SENTU  0x7fc00000u

// Diagonal layout: Dd[b][t][i], t=i+j, row stride 512; 1024 rows/batch + pad.
#define TROWS   1024
#define BSTRIDE (TROWS * NM)
__device__ float g_Dd[(size_t)BATCH * BSTRIDE + 16384];

// buf row layout: 576 floats per row; index 32+c holds boundary col c.
#define ROWLEN 576

__device__ __forceinline__ float ex2f(float x) {
    float r; asm("ex2.approx.f32 %0, %1;" : "=f"(r) : "f"(x)); return r;
}
__device__ __forceinline__ float lg2f(float x) {
    float r; asm("lg2.approx.f32 %0, %1;" : "=f"(r) : "f"(x)); return r;
}
// Raw spin (no BSSY/BSYNC): wait until *p != SENTU.
__device__ __forceinline__ float spin_ld(const float* p) {
    unsigned a = (unsigned)__cvta_generic_to_shared(p);
    unsigned v;
    asm volatile(
        "{\n\t.reg .pred sp;\n"
        "SPIN%=:\n\t"
        "ld.volatile.shared.b32 %0, [%1];\n\t"
        "setp.eq.u32 sp, %0, 0x7fc00000;\n\t"
        "@sp bra SPIN%=;\n\t}"
        : "=r"(v) : "r"(a) : "memory");
    return __uint_as_float(v);
}

// ---------------------------------------------------------------------------
// Kernel 1: Dd[b][i+j][i] = sqdist * log2(e). 64x64 tiles, 4x4 microtiles.
// ---------------------------------------------------------------------------
__global__ void __launch_bounds__(256) pairdist_kernel(
    const float* __restrict__ X, const float* __restrict__ Y)
{
    __shared__ __align__(16) float Xs[64 * 68];
    __shared__ __align__(16) float Ys[64 * 68];
    __shared__ __align__(16) float x2s[64];
    __shared__ __align__(16) float y2s[64];
    __shared__ __align__(16) float stage[64 * 64];

    const int b  = blockIdx.z;
    const int i0 = blockIdx.x * 64;
    const int j0 = blockIdx.y * 64;
    const int tid = threadIdx.x;

    const float* Xb = X + ((size_t)b * NM + i0) * DIMK;
    const float* Yb = Y + ((size_t)b * NM + j0) * DIMK;

    for (int t = tid; t < 64 * 64; t += 256) {
        int r = t >> 6, k = t & 63;
        Xs[k * 68 + r] = Xb[r * DIMK + k];
        Ys[k * 68 + r] = Yb[r * DIMK + k];
    }
    __syncthreads();

    if (tid < 128) {
        int r = tid & 63;
        const float* S = (tid < 64) ? Xs : Ys;
        float acc = 0.f;
        #pragma unroll 8
        for (int k = 0; k < 64; ++k) { float v = S[k * 68 + r]; acc += v * v; }
        if (tid < 64) x2s[r] = acc; else y2s[r] = acc;
    }
    __syncthreads();

    const int tx = tid & 15, ty = tid >> 4;
    float acc[4][4];
    #pragma unroll
    for (int a = 0; a < 4; ++a)
        #pragma unroll
        for (int c = 0; c < 4; ++c) acc[a][c] = 0.f;

    #pragma unroll 8
    for (int k = 0; k < 64; ++k) {
        float4 xv = *(const float4*)&Xs[k * 68 + 4 * tx];
        float4 yv = *(const float4*)&Ys[k * 68 + 4 * ty];
        float xr[4] = {xv.x, xv.y, xv.z, xv.w};
        float yr[4] = {yv.x, yv.y, yv.z, yv.w};
        #pragma unroll
        for (int jj = 0; jj < 4; ++jj)
            #pragma unroll
            for (int ii = 0; ii < 4; ++ii)
                acc[jj][ii] += yr[jj] * xr[ii];
    }

    const float L2E = 1.4426950408889634f;
    float4 x2v = *(const float4*)&x2s[4 * tx];
    float xr2[4] = {x2v.x, x2v.y, x2v.z, x2v.w};
    #pragma unroll
    for (int jj = 0; jj < 4; ++jj) {
        float y2 = y2s[4 * ty + jj];
        #pragma unroll
        for (int ii = 0; ii < 4; ++ii)
            stage[(4 * ty + jj) * 64 + 4 * tx + ii] =
                (xr2[ii] + y2 - 2.f * acc[jj][ii]) * L2E;
    }
    __syncthreads();

    const int w    = tid >> 5;
    const int lane = tid & 31;
    const int tbase = i0 + j0;
    float* gout = g_Dd + (size_t)b * BSTRIDE;
    for (int td = w; td < 127; td += 8) {
        int lo = td > 63 ? td - 63 : 0;
        int hi = td < 63 ? td : 63;
        for (int il = lo + lane; il <= hi; il += 32) {
            float v = stage[(td - il) * 64 + il];
            gout[(size_t)(tbase + td) * NM + i0 + il] = v;
        }
    }
}

// ---------------------------------------------------------------------------
// Kernel 2: soft-DTW wavefront, 16 warps/CTA, 1 CTA/batch.
// Lane k of warp w owns row 32w+k; step s computes col j=s-lane.
// Boundary rows stream via smem; 8-col chunked poll; branchless hot loop.
// ---------------------------------------------------------------------------
__global__ void __launch_bounds__(512, 1) sdtw_kernel(float* __restrict__ out)
{
    __shared__ __align__(16) float buf[(WARPS + 1) * ROWLEN];

    const int b    = blockIdx.x;
    const int tid  = threadIdx.x;
    const int w    = tid >> 5;
    const int lane = tid & 31;
    const bool is0  = (lane == 0);
    const bool is31 = (lane == 31);

    // Init: row 0 all BIG; rows >=1: sentinel for col region [32, 544), BIG elsewhere.
    for (int t = tid; t < (WARPS + 1) * ROWLEN; t += 512) {
        int row = t / ROWLEN, col = t % ROWLEN;
        bool sent = (row >= 1) && (col >= 32) && (col < 32 + NM);
        buf[t] = sent ? __uint_as_float(SENTU) : BIGF;
    }
    __syncthreads();

    // D prefetch ring: consume row 32w+s at step s; prefetch 8 ahead.
    const float* dp = g_Dd + (size_t)b * BSTRIDE + (size_t)(32 * w + 8) * NM + 32 * w + lane;
    float dring[8];
    #pragma unroll
    for (int p = 0; p < 8; ++p) dring[p] = dp[(p - 8) * NM];

    // Boundary pointers
    const float* brow = &buf[w * ROWLEN];              // consumer row (cols at 32+c)
    float*       prow = &buf[(w + 1) * ROWLEN + 1];    // producer base: index 1+s

    // Initial chunk: cols 0..7
    float bnd[8];
    {
        (void)spin_ld(brow + 39);
        float4 c0 = *(const float4*)(brow + 32);
        float4 c1 = *(const float4*)(brow + 36);
        bnd[0]=c0.x; bnd[1]=c0.y; bnd[2]=c0.z; bnd[3]=c0.w;
        bnd[4]=c1.x; bnd[5]=c1.y; bnd[6]=c1.z; bnd[7]=c1.w;
    }

    float res  = 0.f;
    float left = BIGF;
    float up1  = is0 ? bnd[0] : BIGF;
    float up2  = (tid == 0) ? 0.0f : BIGF;
    float pm   = fminf(up1, up2);

    for (int B = 0; B < 544; B += 8) {
        #pragma unroll
        for (int u = 0; u < 8; ++u) {
            float d = dring[u];
            dring[u] = dp[u * NM];                       // prefetch row +8

            float m  = fminf(pm, left);
            float e0 = ex2f(m - up2);
            float e1 = ex2f(m - up1);
            float e2 = ex2f(m - left);
            float lg = lg2f((e0 + e1) + e2);
            float v  = (d + m) - lg;

            if (u == 6) { if (B == 536) res = v; }       // s==542: R[511][511] on tid 511

            if (is31) *(volatile float*)(prow + B + u) = v;   // boundary stream

            float sh = __shfl_up_sync(0xffffffffu, v, 1);

            if (u == 7) {                                // load chunk for next block
                (void)spin_ld(brow + 39 + (B + 8));
                float4 c0 = *(const float4*)(brow + 32 + (B + 8));
                float4 c1 = *(const float4*)(brow + 36 + (B + 8));
                bnd[0]=c0.x; bnd[1]=c0.y; bnd[2]=c0.z; bnd[3]=c0.w;
                bnd[4]=c1.x; bnd[5]=c1.y; bnd[6]=c1.z; bnd[7]=c1.w;
            }

            up2  = up1;
            up1  = is0 ? bnd[(u + 1) & 7] : sh;
            left = v;
            pm   = fminf(up1, up2);
        }
        dp += 8 * NM;
    }

    if (tid == 511)
        out[b] = res * 0.69314718055994531f;             // log2 -> natural domain
}

extern "C" void kernel_launch(void* const* d_in, const int* in_sizes, int n_in,
                              void* d_out, int out_size)
{
    (void)in_sizes; (void)n_in; (void)out_size;
    const float* X = (const float*)d_in[0];
    const float* Y = (const float*)d_in[1];
    float* out = (float*)d_out;

    dim3 g1(NM / 64, NM / 64, BATCH);
    pairdist_kernel<<<g1, 256>>>(X, Y);
    sdtw_kernel<<<BATCH, 512>>>(out);
}